// round 3
// baseline (speedup 1.0000x reference)
#include <cuda_runtime.h>

#define BATCH    4
#define NLAB     8
#define VOX      (64*160*160)       // 1,638,400 voxels per sample
#define V4       (VOX/4)            // 409,600 float4 chunks per sample
#define BLOCKS_X 200
#define THREADS  256
#define STRIDE   (BLOCKS_X*THREADS) // 51,200 ; V4 / STRIDE == 8 exactly
#define NSTAT    17                 // T, s[1..8], c[1..8]

// Per-block partials: [batch*17 + stat][block]. Fully overwritten every call.
__device__ float g_part[BATCH*NSTAT][BLOCKS_X];

__device__ __forceinline__ float sigm_p1(float x0, float x1) {
    // softmax over 2 classes: p1 = 1 / (1 + exp(x0 - x1))
    return __fdividef(1.f, 1.f + __expf(x0 - x1));
}

__global__ void __launch_bounds__(THREADS, 2)
reduce_kernel(const float* __restrict__ x, const int* __restrict__ ml) {
    const int b = blockIdx.y;
    const float4* __restrict__ x0v = reinterpret_cast<const float4*>(x + (size_t)b * 2 * VOX);
    const float4* __restrict__ x1v = reinterpret_cast<const float4*>(x + (size_t)b * 2 * VOX + VOX);
    const int4*   __restrict__ mlv = reinterpret_cast<const int4*>(ml + (size_t)b * VOX);

    const int i0 = blockIdx.x * THREADS + threadIdx.x;

    float tSum = 0.f;
    float s[NLAB], c[NLAB];
#pragma unroll
    for (int i = 0; i < NLAB; i++) { s[i] = 0.f; c[i] = 0.f; }

#pragma unroll
    for (int k = 0; k < 8; k += 4) {
        // Front-batch all 12 vector loads (high MLP)
        float4 A0 = x0v[i0 + (k+0)*STRIDE];
        float4 A1 = x0v[i0 + (k+1)*STRIDE];
        float4 A2 = x0v[i0 + (k+2)*STRIDE];
        float4 A3 = x0v[i0 + (k+3)*STRIDE];
        float4 B0 = x1v[i0 + (k+0)*STRIDE];
        float4 B1 = x1v[i0 + (k+1)*STRIDE];
        float4 B2 = x1v[i0 + (k+2)*STRIDE];
        float4 B3 = x1v[i0 + (k+3)*STRIDE];
        int4   L0 = mlv[i0 + (k+0)*STRIDE];
        int4   L1 = mlv[i0 + (k+1)*STRIDE];
        int4   L2 = mlv[i0 + (k+2)*STRIDE];
        int4   L3 = mlv[i0 + (k+3)*STRIDE];

#pragma unroll
        for (int j = 0; j < 4; j++) {
            float4 A = (j==0)?A0:(j==1)?A1:(j==2)?A2:A3;
            float4 Bv= (j==0)?B0:(j==1)?B1:(j==2)?B2:B3;
            int4   L = (j==0)?L0:(j==1)?L1:(j==2)?L2:L3;

            float p0 = sigm_p1(A.x, Bv.x);
            float p1 = sigm_p1(A.y, Bv.y);
            float p2 = sigm_p1(A.z, Bv.z);
            float p3 = sigm_p1(A.w, Bv.w);
            tSum += (p0 + p1) + (p2 + p3);

            if ((L.x | L.y | L.z | L.w) != 0) {   // ~9% of chunks carry labels
                float pv[4] = {p0, p1, p2, p3};
                int   lv[4] = {L.x, L.y, L.z, L.w};
#pragma unroll
                for (int v = 0; v < 4; v++) {
                    int lab = lv[v];
#pragma unroll
                    for (int q = 1; q <= NLAB; q++) {
                        if (lab == q) { s[q-1] += pv[v]; c[q-1] += 1.f; }
                    }
                }
            }
        }
    }

    // ---- intra-warp reduction (17 floats) ----
#pragma unroll
    for (int o = 16; o > 0; o >>= 1) {
        tSum += __shfl_xor_sync(0xffffffffu, tSum, o);
#pragma unroll
        for (int i = 0; i < NLAB; i++) {
            s[i] += __shfl_xor_sync(0xffffffffu, s[i], o);
            c[i] += __shfl_xor_sync(0xffffffffu, c[i], o);
        }
    }

    // ---- intra-block combine via shared atomics ----
    __shared__ float sh[NSTAT];
    if (threadIdx.x < NSTAT) sh[threadIdx.x] = 0.f;
    __syncthreads();
    if ((threadIdx.x & 31) == 0) {
        atomicAdd(&sh[0], tSum);
#pragma unroll
        for (int i = 0; i < NLAB; i++) {
            atomicAdd(&sh[1 + i],        s[i]);
            atomicAdd(&sh[1 + NLAB + i], c[i]);
        }
    }
    __syncthreads();

    if (threadIdx.x < NSTAT)
        g_part[b * NSTAT + threadIdx.x][blockIdx.x] = sh[threadIdx.x];
}

__global__ void __launch_bounds__(256)
finalize_kernel(float* __restrict__ out) {
    __shared__ double sh[BATCH * NSTAT];
    const int w    = threadIdx.x >> 5;   // 8 warps
    const int lane = threadIdx.x & 31;

    // 8 warps reduce 68 stats (200 partials each) in double
    for (int st = w; st < BATCH * NSTAT; st += 8) {
        double acc = 0.0;
        for (int blk = lane; blk < BLOCKS_X; blk += 32)
            acc += (double)g_part[st][blk];
#pragma unroll
        for (int o = 16; o > 0; o >>= 1)
            acc += __shfl_xor_sync(0xffffffffu, acc, o);
        if (lane == 0) sh[st] = acc;
    }
    __syncthreads();

    if (threadIdx.x != 0) return;

    const double A = 0.3, Bq = 0.7;     // TV_ALPHA, TV_BETA
    const double Vd = (double)VOX;
    double mainAcc = 0.0, blobAcc = 0.0;

    for (int b = 0; b < BATCH; b++) {
        const double* st = &sh[b * NSTAT];
        double T = st[0];
        double S[NLAB], C[NLAB], sSum = 0.0, cSum = 0.0;
        for (int i = 0; i < NLAB; i++) {
            S[i] = st[1 + i];
            C[i] = st[1 + NLAB + i];
            sSum += S[i]; cSum += C[i];
        }
        double cnt0 = Vd - cSum;
        double s0   = T - sSum;

        // main (unmasked softmax) Tversky, classes 1 and 0
        {
            double tp = sSum, P = T, G = cSum;
            double den = tp + A * (P - tp) + Bq * (G - tp);
            den = den < 1e-8 ? 1e-8 : den;
            mainAcc += tp / den;

            double tp0 = cnt0 - s0, P0 = Vd - T, G0 = cnt0;
            double den0 = tp0 + A * (P0 - tp0) + Bq * (G0 - tp0);
            den0 = den0 < 1e-8 ? 1e-8 : den0;
            mainAcc += tp0 / den0;
        }

        // blob losses: masked voxels (other blobs) have softmax p = 0.5 exactly
        for (int k = 0; k < NLAB; k++) {
            double M = cSum - C[k];

            double tp = S[k];
            double P  = S[k] + s0 + 0.5 * M;
            double G  = C[k];
            double den = tp + A * (P - tp) + Bq * (G - tp);
            den = den < 1e-8 ? 1e-8 : den;
            blobAcc += tp / den;

            double tp0 = (cnt0 - s0) + 0.5 * M;
            double P0  = Vd - P;
            double G0  = Vd - C[k];
            double den0 = tp0 + A * (P0 - tp0) + Bq * (G0 - tp0);
            den0 = den0 < 1e-8 ? 1e-8 : den0;
            blobAcc += tp0 / den0;
        }
    }

    double main_loss = -mainAcc / (2.0 * BATCH);               // ×(MAIN_WEIGHT·CRIT)=1
    double blob_loss = -0.25 * blobAcc / ((double)NLAB * BATCH);
    out[0] = (float)(main_loss + blob_loss);
}

extern "C" void kernel_launch(void* const* d_in, const int* in_sizes, int n_in,
                              void* d_out, int out_size) {
    const float* x  = (const float*)d_in[0];
    const int*   ml = (const int*)d_in[1];
    float* out = (float*)d_out;

    dim3 grid(BLOCKS_X, BATCH);
    reduce_kernel<<<grid, THREADS>>>(x, ml);
    finalize_kernel<<<1, 256>>>(out);
}

// round 4
// speedup vs baseline: 1.9412x; 1.9412x over previous
#include <cuda_runtime.h>

#define BATCH    4
#define NLAB     8
#define VOX      (64*160*160)       // 1,638,400 voxels per sample
#define V4       (VOX/4)            // 409,600 float4 chunks per sample
#define BLOCKS_X 200
#define THREADS  256
#define STRIDE   (BLOCKS_X*THREADS) // 51,200 ; V4 / STRIDE == 8 exactly
#define NSTAT    17                 // T, s[1..8], c[1..8]
#define NTERMS   (BATCH*18)         // 72 Tversky ratio terms

// Per-block partials: [batch*17 + stat][block]. Fully overwritten every call.
__device__ float g_part[BATCH*NSTAT][BLOCKS_X];

__device__ __forceinline__ float sigm_p1(float x0, float x1) {
    // softmax over 2 classes: p1 = 1 / (1 + exp(x0 - x1))
    return __fdividef(1.f, 1.f + __expf(x0 - x1));
}

__global__ void __launch_bounds__(THREADS, 2)
reduce_kernel(const float* __restrict__ x, const int* __restrict__ ml) {
    const int b = blockIdx.y;
    const float4* __restrict__ x0v = reinterpret_cast<const float4*>(x + (size_t)b * 2 * VOX);
    const float4* __restrict__ x1v = reinterpret_cast<const float4*>(x + (size_t)b * 2 * VOX + VOX);
    const int4*   __restrict__ mlv = reinterpret_cast<const int4*>(ml + (size_t)b * VOX);

    const int i0 = blockIdx.x * THREADS + threadIdx.x;

    float tSum = 0.f;
    float s[NLAB], c[NLAB];
#pragma unroll
    for (int i = 0; i < NLAB; i++) { s[i] = 0.f; c[i] = 0.f; }

#pragma unroll
    for (int k = 0; k < 8; k += 4) {
        // Front-batch all 12 vector loads (high MLP)
        float4 A0 = x0v[i0 + (k+0)*STRIDE];
        float4 A1 = x0v[i0 + (k+1)*STRIDE];
        float4 A2 = x0v[i0 + (k+2)*STRIDE];
        float4 A3 = x0v[i0 + (k+3)*STRIDE];
        float4 B0 = x1v[i0 + (k+0)*STRIDE];
        float4 B1 = x1v[i0 + (k+1)*STRIDE];
        float4 B2 = x1v[i0 + (k+2)*STRIDE];
        float4 B3 = x1v[i0 + (k+3)*STRIDE];
        int4   L0 = mlv[i0 + (k+0)*STRIDE];
        int4   L1 = mlv[i0 + (k+1)*STRIDE];
        int4   L2 = mlv[i0 + (k+2)*STRIDE];
        int4   L3 = mlv[i0 + (k+3)*STRIDE];

#pragma unroll
        for (int j = 0; j < 4; j++) {
            float4 A = (j==0)?A0:(j==1)?A1:(j==2)?A2:A3;
            float4 Bv= (j==0)?B0:(j==1)?B1:(j==2)?B2:B3;
            int4   L = (j==0)?L0:(j==1)?L1:(j==2)?L2:L3;

            float p0 = sigm_p1(A.x, Bv.x);
            float p1 = sigm_p1(A.y, Bv.y);
            float p2 = sigm_p1(A.z, Bv.z);
            float p3 = sigm_p1(A.w, Bv.w);
            tSum += (p0 + p1) + (p2 + p3);

            if ((L.x | L.y | L.z | L.w) != 0) {   // ~9% of chunks carry labels
                float pv[4] = {p0, p1, p2, p3};
                int   lv[4] = {L.x, L.y, L.z, L.w};
#pragma unroll
                for (int v = 0; v < 4; v++) {
                    int lab = lv[v];
#pragma unroll
                    for (int q = 1; q <= NLAB; q++) {
                        if (lab == q) { s[q-1] += pv[v]; c[q-1] += 1.f; }
                    }
                }
            }
        }
    }

    // ---- intra-warp reduction (17 floats) ----
#pragma unroll
    for (int o = 16; o > 0; o >>= 1) {
        tSum += __shfl_xor_sync(0xffffffffu, tSum, o);
#pragma unroll
        for (int i = 0; i < NLAB; i++) {
            s[i] += __shfl_xor_sync(0xffffffffu, s[i], o);
            c[i] += __shfl_xor_sync(0xffffffffu, c[i], o);
        }
    }

    // ---- intra-block combine via shared atomics ----
    __shared__ float sh[NSTAT];
    if (threadIdx.x < NSTAT) sh[threadIdx.x] = 0.f;
    __syncthreads();
    if ((threadIdx.x & 31) == 0) {
        atomicAdd(&sh[0], tSum);
#pragma unroll
        for (int i = 0; i < NLAB; i++) {
            atomicAdd(&sh[1 + i],        s[i]);
            atomicAdd(&sh[1 + NLAB + i], c[i]);
        }
    }
    __syncthreads();

    if (threadIdx.x < NSTAT)
        g_part[b * NSTAT + threadIdx.x][blockIdx.x] = sh[threadIdx.x];
}

__global__ void __launch_bounds__(256)
finalize_kernel(float* __restrict__ out) {
    __shared__ double sh[BATCH * NSTAT];   // T, S[8], C[8] per batch
    __shared__ double shSum[BATCH * 2];    // sSum, cSum per batch
    __shared__ double shWarp[8];

    const int w    = threadIdx.x >> 5;   // 8 warps
    const int lane = threadIdx.x & 31;

    // Stage 1: 8 warps reduce 68 stats (200 partials each) in double
    for (int st = w; st < BATCH * NSTAT; st += 8) {
        double acc = 0.0;
        for (int blk = lane; blk < BLOCKS_X; blk += 32)
            acc += (double)g_part[st][blk];
#pragma unroll
        for (int o = 16; o > 0; o >>= 1)
            acc += __shfl_xor_sync(0xffffffffu, acc, o);
        if (lane == 0) sh[st] = acc;
    }
    __syncthreads();

    // Stage 2: per-batch sums (4 threads)
    if (threadIdx.x < BATCH * 2) {
        int b    = threadIdx.x >> 1;
        int kind = threadIdx.x & 1;       // 0 -> sSum, 1 -> cSum
        const double* st = &sh[b * NSTAT + 1 + kind * NLAB];
        double a = 0.0;
#pragma unroll
        for (int i = 0; i < NLAB; i++) a += st[i];
        shSum[threadIdx.x] = a;
    }
    __syncthreads();

    // Stage 3: 72 Tversky ratio terms, one per thread, all divides in flight
    const double A = 0.3, Bq = 0.7;       // TV_ALPHA, TV_BETA
    const double Vd = (double)VOX;
    double term = 0.0;

    if (threadIdx.x < NTERMS) {
        int b = threadIdx.x / 18;
        int u = threadIdx.x % 18;
        const double* st = &sh[b * NSTAT];
        double T    = st[0];
        double sSum = shSum[b * 2 + 0];
        double cSum = shSum[b * 2 + 1];
        double cnt0 = Vd - cSum;
        double s0   = T - sSum;

        double tp, P, G, weight;
        if (u < 2) {
            // main (unmasked softmax): u==0 class1, u==1 class0
            weight = -1.0 / (2.0 * BATCH);          // = -1/8
            if (u == 0) { tp = sSum;      P = T;      G = cSum; }
            else        { tp = cnt0 - s0; P = Vd - T; G = cnt0; }
        } else {
            // blob k, masked voxels (other blobs) contribute p = 0.5 exactly
            weight = -0.25 / ((double)NLAB * BATCH); // = -1/128
            int k  = (u - 2) >> 1;
            int cl = (u - 2) & 1;                    // 0 -> class1, 1 -> class0
            double Sk = st[1 + k];
            double Ck = st[1 + NLAB + k];
            double M  = cSum - Ck;
            double P1 = Sk + s0 + 0.5 * M;
            if (cl == 0) { tp = Sk;                      P = P1;      G = Ck; }
            else         { tp = (cnt0 - s0) + 0.5 * M;   P = Vd - P1; G = Vd - Ck; }
        }
        double den = tp + A * (P - tp) + Bq * (G - tp);
        den = den < 1e-8 ? 1e-8 : den;
        term = weight * (tp / den);
    }

    // Stage 4: tree-reduce the 72 weighted terms (first 3 warps carry data)
#pragma unroll
    for (int o = 16; o > 0; o >>= 1)
        term += __shfl_xor_sync(0xffffffffu, term, o);
    if (lane == 0) shWarp[w] = term;
    __syncthreads();

    if (threadIdx.x == 0)
        out[0] = (float)(shWarp[0] + shWarp[1] + shWarp[2]);
}

extern "C" void kernel_launch(void* const* d_in, const int* in_sizes, int n_in,
                              void* d_out, int out_size) {
    const float* x  = (const float*)d_in[0];
    const int*   ml = (const int*)d_in[1];
    float* out = (float*)d_out;

    dim3 grid(BLOCKS_X, BATCH);
    reduce_kernel<<<grid, THREADS>>>(x, ml);
    finalize_kernel<<<1, 256>>>(out);
}

// round 5
// speedup vs baseline: 3.3673x; 1.7347x over previous
#include <cuda_runtime.h>

#define BATCH    4
#define NLAB     8
#define VOX      (64*160*160)       // 1,638,400 voxels per sample
#define V4       (VOX/4)            // 409,600 float4 chunks per sample
#define BLOCKS_X 200
#define THREADS  256
#define STRIDE   (BLOCKS_X*THREADS) // 51,200 ; V4 / STRIDE == 8 exactly
#define NSTAT    17                 // T, s[1..8], c[1..8]
#define NTERMS   (BATCH*18)         // 72 Tversky ratio terms
#define TOTAL_BLOCKS (BLOCKS_X*BATCH)

// Per-block partials: [batch*17 + stat][block]. Fully overwritten every call.
__device__ float g_part[BATCH*NSTAT][BLOCKS_X];
__device__ int   g_count = 0;       // completion counter; reset in-kernel each call

__device__ __forceinline__ float sigm_p1(float x0, float x1) {
    // softmax over 2 classes: p1 = 1 / (1 + exp(x0 - x1))
    return __fdividef(1.f, 1.f + __expf(x0 - x1));
}

__global__ void __launch_bounds__(THREADS, 2)
fused_kernel(const float* __restrict__ x, const int* __restrict__ ml,
             float* __restrict__ out) {
    const int b = blockIdx.y;
    const float4* __restrict__ x0v = reinterpret_cast<const float4*>(x + (size_t)b * 2 * VOX);
    const float4* __restrict__ x1v = reinterpret_cast<const float4*>(x + (size_t)b * 2 * VOX + VOX);
    const int4*   __restrict__ mlv = reinterpret_cast<const int4*>(ml + (size_t)b * VOX);

    const int i0 = blockIdx.x * THREADS + threadIdx.x;

    float tSum = 0.f;
    float s[NLAB], c[NLAB];
#pragma unroll
    for (int i = 0; i < NLAB; i++) { s[i] = 0.f; c[i] = 0.f; }

#pragma unroll
    for (int k = 0; k < 8; k += 4) {
        // Front-batch all 12 vector loads (high MLP)
        float4 A0 = x0v[i0 + (k+0)*STRIDE];
        float4 A1 = x0v[i0 + (k+1)*STRIDE];
        float4 A2 = x0v[i0 + (k+2)*STRIDE];
        float4 A3 = x0v[i0 + (k+3)*STRIDE];
        float4 B0 = x1v[i0 + (k+0)*STRIDE];
        float4 B1 = x1v[i0 + (k+1)*STRIDE];
        float4 B2 = x1v[i0 + (k+2)*STRIDE];
        float4 B3 = x1v[i0 + (k+3)*STRIDE];
        int4   L0 = mlv[i0 + (k+0)*STRIDE];
        int4   L1 = mlv[i0 + (k+1)*STRIDE];
        int4   L2 = mlv[i0 + (k+2)*STRIDE];
        int4   L3 = mlv[i0 + (k+3)*STRIDE];

#pragma unroll
        for (int j = 0; j < 4; j++) {
            float4 A = (j==0)?A0:(j==1)?A1:(j==2)?A2:A3;
            float4 Bv= (j==0)?B0:(j==1)?B1:(j==2)?B2:B3;
            int4   L = (j==0)?L0:(j==1)?L1:(j==2)?L2:L3;

            float p0 = sigm_p1(A.x, Bv.x);
            float p1 = sigm_p1(A.y, Bv.y);
            float p2 = sigm_p1(A.z, Bv.z);
            float p3 = sigm_p1(A.w, Bv.w);
            tSum += (p0 + p1) + (p2 + p3);

            if ((L.x | L.y | L.z | L.w) != 0) {   // ~9% of chunks carry labels
                float pv[4] = {p0, p1, p2, p3};
                int   lv[4] = {L.x, L.y, L.z, L.w};
#pragma unroll
                for (int v = 0; v < 4; v++) {
                    int lab = lv[v];
#pragma unroll
                    for (int q = 1; q <= NLAB; q++) {
                        if (lab == q) { s[q-1] += pv[v]; c[q-1] += 1.f; }
                    }
                }
            }
        }
    }

    // ---- intra-warp reduction (17 floats) ----
#pragma unroll
    for (int o = 16; o > 0; o >>= 1) {
        tSum += __shfl_xor_sync(0xffffffffu, tSum, o);
#pragma unroll
        for (int i = 0; i < NLAB; i++) {
            s[i] += __shfl_xor_sync(0xffffffffu, s[i], o);
            c[i] += __shfl_xor_sync(0xffffffffu, c[i], o);
        }
    }

    // ---- intra-block combine via shared atomics ----
    __shared__ float shP[NSTAT];
    __shared__ int   shLast;
    if (threadIdx.x < NSTAT) shP[threadIdx.x] = 0.f;
    __syncthreads();
    if ((threadIdx.x & 31) == 0) {
        atomicAdd(&shP[0], tSum);
#pragma unroll
        for (int i = 0; i < NLAB; i++) {
            atomicAdd(&shP[1 + i],        s[i]);
            atomicAdd(&shP[1 + NLAB + i], c[i]);
        }
    }
    __syncthreads();

    if (threadIdx.x < NSTAT)
        g_part[b * NSTAT + threadIdx.x][blockIdx.x] = shP[threadIdx.x];

    // ---- completion protocol: last block finalizes ----
    __threadfence();
    __syncthreads();
    if (threadIdx.x == 0) {
        int done = atomicAdd(&g_count, 1);
        shLast = (done == TOTAL_BLOCKS - 1) ? 1 : 0;
    }
    __syncthreads();
    if (!shLast) return;
    if (threadIdx.x == 0) g_count = 0;   // reset for next graph replay

    // ================= FINALIZE (single last block, 8 warps) =================
    __shared__ double shD[BATCH * NSTAT];
    __shared__ double shSum[BATCH * 2];
    __shared__ double shWarp[8];

    const int w    = threadIdx.x >> 5;
    const int lane = threadIdx.x & 31;

    // Stage 1: reduce 68 stats x 200 partials; independent batched float loads
    for (int st = w; st < BATCH * NSTAT; st += 8) {
        float p[7];
#pragma unroll
        for (int i = 0; i < 7; i++) {
            int blk = lane + 32 * i;
            p[i] = (blk < BLOCKS_X) ? g_part[st][blk] : 0.f;
        }
        float a = ((p[0] + p[1]) + (p[2] + p[3])) + ((p[4] + p[5]) + p[6]);
#pragma unroll
        for (int o = 16; o > 0; o >>= 1)
            a += __shfl_xor_sync(0xffffffffu, a, o);
        if (lane == 0) shD[st] = (double)a;
    }
    __syncthreads();

    // Stage 2: per-batch sums (8 threads)
    if (threadIdx.x < BATCH * 2) {
        int bb   = threadIdx.x >> 1;
        int kind = threadIdx.x & 1;       // 0 -> sSum, 1 -> cSum
        const double* st = &shD[bb * NSTAT + 1 + kind * NLAB];
        double a = 0.0;
#pragma unroll
        for (int i = 0; i < NLAB; i++) a += st[i];
        shSum[threadIdx.x] = a;
    }
    __syncthreads();

    // Stage 3: 72 weighted Tversky ratio terms, one per thread
    const double A = 0.3, Bq = 0.7;       // TV_ALPHA, TV_BETA
    const double Vd = (double)VOX;
    double term = 0.0;

    if (threadIdx.x < NTERMS) {
        int bb = threadIdx.x / 18;
        int u  = threadIdx.x % 18;
        const double* st = &shD[bb * NSTAT];
        double T    = st[0];
        double sSum = shSum[bb * 2 + 0];
        double cSum = shSum[bb * 2 + 1];
        double cnt0 = Vd - cSum;
        double s0   = T - sSum;

        double tp, P, G, weight;
        if (u < 2) {
            // main (unmasked softmax): u==0 class1, u==1 class0
            weight = -1.0 / (2.0 * BATCH);          // = -1/8 (MAIN_WEIGHT*CRIT=1)
            if (u == 0) { tp = sSum;      P = T;      G = cSum; }
            else        { tp = cnt0 - s0; P = Vd - T; G = cnt0; }
        } else {
            // blob k: masked voxels (other blobs) have softmax p = 0.5 exactly
            weight = -0.25 / ((double)NLAB * BATCH); // = -1/128
            int k  = (u - 2) >> 1;
            int cl = (u - 2) & 1;
            double Sk = st[1 + k];
            double Ck = st[1 + NLAB + k];
            double M  = cSum - Ck;
            double P1 = Sk + s0 + 0.5 * M;
            if (cl == 0) { tp = Sk;                    P = P1;      G = Ck; }
            else         { tp = (cnt0 - s0) + 0.5 * M; P = Vd - P1; G = Vd - Ck; }
        }
        double den = tp + A * (P - tp) + Bq * (G - tp);
        den = den < 1e-8 ? 1e-8 : den;
        term = weight * (tp / den);
    }

    // Stage 4: tree-reduce the 72 weighted terms
#pragma unroll
    for (int o = 16; o > 0; o >>= 1)
        term += __shfl_xor_sync(0xffffffffu, term, o);
    if (lane == 0) shWarp[w] = term;
    __syncthreads();

    if (threadIdx.x == 0)
        out[0] = (float)(shWarp[0] + shWarp[1] + shWarp[2]);
}

extern "C" void kernel_launch(void* const* d_in, const int* in_sizes, int n_in,
                              void* d_out, int out_size) {
    const float* x  = (const float*)d_in[0];
    const int*   ml = (const int*)d_in[1];
    float* out = (float*)d_out;

    dim3 grid(BLOCKS_X, BATCH);
    fused_kernel<<<grid, THREADS>>>(x, ml, out);
}